// round 1
// baseline (speedup 1.0000x reference)
#include <cuda_runtime.h>

// LBFGS two-loop recursion. M=32 steps backward + 32 forward, each step:
// full-D dot product (block reduction) + axpy on carry q.
// One CTA per batch b (64 CTAs), 1024 threads, 8 floats (2 float4) per thread.
// q is register-resident. s/y rows for the next step are prefetched into
// registers while the current step's reduction drains, so the per-step
// latency is bounded by the 64KB/CTA HBM stream, not the reduce chain.

#define MM 32
#define BB 64
#define DD 8192
#define NT 1024
#define F4ROW (DD / 4)   // 2048 float4 per (i,b) row; 2 per thread

struct R3 { float a, b, c; };

__device__ __forceinline__ R3 block_reduce3(float v0, float v1, float v2,
                                            float* red) {
    const int tid  = threadIdx.x;
    const int lane = tid & 31;
    const int wid  = tid >> 5;
#pragma unroll
    for (int off = 16; off > 0; off >>= 1) {
        v0 += __shfl_xor_sync(0xffffffffu, v0, off);
        v1 += __shfl_xor_sync(0xffffffffu, v1, off);
        v2 += __shfl_xor_sync(0xffffffffu, v2, off);
    }
    if (lane == 0) { red[wid] = v0; red[32 + wid] = v1; red[64 + wid] = v2; }
    __syncthreads();
    if (wid == 0) {
        float x0 = red[lane];
        float x1 = red[32 + lane];
        float x2 = red[64 + lane];
#pragma unroll
        for (int off = 16; off > 0; off >>= 1) {
            x0 += __shfl_xor_sync(0xffffffffu, x0, off);
            x1 += __shfl_xor_sync(0xffffffffu, x1, off);
            x2 += __shfl_xor_sync(0xffffffffu, x2, off);
        }
        if (lane == 0) { red[96] = x0; red[97] = x1; red[98] = x2; }
    }
    __syncthreads();
    R3 r;
    r.a = red[96];
    r.b = red[97];
    r.c = red[98];
    return r;
}

__device__ __forceinline__ float dot8(float4 a0, float4 a1, float4 b0, float4 b1) {
    return a0.x * b0.x + a0.y * b0.y + a0.z * b0.z + a0.w * b0.w +
           a1.x * b1.x + a1.y * b1.y + a1.z * b1.z + a1.w * b1.w;
}

__device__ __forceinline__ void axpy8(float4& q0, float4& q1, float c,
                                      float4 v0, float4 v1) {
    q0.x += c * v0.x; q0.y += c * v0.y; q0.z += c * v0.z; q0.w += c * v0.w;
    q1.x += c * v1.x; q1.y += c * v1.y; q1.z += c * v1.z; q1.w += c * v1.w;
}

__global__ __launch_bounds__(NT, 1)
void lbfgs_scan_kernel(const float* __restrict__ S,
                       const float* __restrict__ Y,
                       const float* __restrict__ FRC,
                       float* __restrict__ OUT) {
    const int b   = blockIdx.x;
    const int tid = threadIdx.x;

    __shared__ float red[128];
    __shared__ float r_arr[MM];
    __shared__ float a_arr[MM];

    const float4* S4 = (const float4*)S;
    const float4* Y4 = (const float4*)Y;

    // q = -frc
    const float4* F4 = (const float4*)FRC + (size_t)b * F4ROW;
    float4 q0 = F4[tid];
    float4 q1 = F4[tid + NT];
    q0.x = -q0.x; q0.y = -q0.y; q0.z = -q0.z; q0.w = -q0.w;
    q1.x = -q1.x; q1.y = -q1.y; q1.z = -q1.z; q1.w = -q1.w;

    // row base (in float4 units) for history index i of this batch
    auto rowbase = [&](int i) -> size_t {
        return ((size_t)i * BB + b) * (size_t)F4ROW;
    };

    // prefetch current rows for i = M-1
    float4 sc0, sc1, yc0, yc1;
    {
        size_t base = rowbase(MM - 1);
        sc0 = S4[base + tid];
        sc1 = S4[base + tid + NT];
        yc0 = Y4[base + tid];
        yc1 = Y4[base + tid + NT];
    }

    float gscale = 1.0f;

    // ---------------- backward pass: i = M-1 .. 0 ----------------
#pragma unroll 1
    for (int step = 0; step < MM; ++step) {
        const int i     = MM - 1 - step;
        const int inext = (i > 0) ? (i - 1) : 0;  // i==0: preload row 0 for fwd

        // issue next-step loads ASAP; they drain under the reduction below
        const size_t nb = rowbase(inext);
        float4 sn0 = S4[nb + tid];
        float4 sn1 = S4[nb + tid + NT];
        float4 yn0 = Y4[nb + tid];
        float4 yn1 = Y4[nb + tid + NT];

        float dsy = dot8(sc0, sc1, yc0, yc1);
        float dsq = dot8(sc0, sc1, q0, q1);
        float dyy = 0.0f;
        if (i == MM - 1) dyy = dot8(yc0, yc1, yc0, yc1);

        R3 t = block_reduce3(dsy, dsq, dyy, red);

        const float r = 1.0f / t.a;
        const float a = r * t.b;
        if (tid == 0) { r_arr[i] = r; a_arr[i] = a; }
        if (i == MM - 1) gscale = t.a / t.c;

        // q -= a * y_i
        axpy8(q0, q1, -a, yc0, yc1);

        sc0 = sn0; sc1 = sn1; yc0 = yn0; yc1 = yn1;
    }

    // q *= g
    q0.x *= gscale; q0.y *= gscale; q0.z *= gscale; q0.w *= gscale;
    q1.x *= gscale; q1.y *= gscale; q1.z *= gscale; q1.w *= gscale;

    // ---------------- forward pass: i = 0 .. M-1 ----------------
    // current rows = i=0 (prefetched in last backward step)
#pragma unroll 1
    for (int i = 0; i < MM; ++i) {
        const int inext = (i < MM - 1) ? (i + 1) : (MM - 1);
        const size_t nb = rowbase(inext);
        float4 sn0 = S4[nb + tid];
        float4 sn1 = S4[nb + tid + NT];
        float4 yn0 = Y4[nb + tid];
        float4 yn1 = Y4[nb + tid + NT];

        float dyq = dot8(yc0, yc1, q0, q1);

        R3 t = block_reduce3(dyq, 0.0f, 0.0f, red);

        // reads after the reduce's __syncthreads -> backward's writes visible
        const float bi = r_arr[i] * t.a;
        const float ci = a_arr[i] - bi;

        // q += ci * s_i
        axpy8(q0, q1, ci, sc0, sc1);

        sc0 = sn0; sc1 = sn1; yc0 = yn0; yc1 = yn1;
    }

    // out = -q
    float4 o0, o1;
    o0.x = -q0.x; o0.y = -q0.y; o0.z = -q0.z; o0.w = -q0.w;
    o1.x = -q1.x; o1.y = -q1.y; o1.z = -q1.z; o1.w = -q1.w;
    float4* O4 = (float4*)OUT + (size_t)b * F4ROW;
    O4[tid]      = o0;
    O4[tid + NT] = o1;
}

extern "C" void kernel_launch(void* const* d_in, const int* in_sizes, int n_in,
                              void* d_out, int out_size) {
    const float* S   = (const float*)d_in[0];  // (M, B, D) fp32
    const float* Y   = (const float*)d_in[1];  // (M, B, D) fp32
    const float* FRC = (const float*)d_in[2];  // (B, D)    fp32
    float* OUT = (float*)d_out;                // (B, D)    fp32

    lbfgs_scan_kernel<<<BB, NT>>>(S, Y, FRC, OUT);
}